// round 1
// baseline (speedup 1.0000x reference)
#include <cuda_runtime.h>
#include <cstddef>

#define NN 50000
#define EE 800000

// ---------------- scratch (static __device__ — no allocation allowed) ----------------
__device__ float g_s1 [(size_t)NN * 128];   // spmm(x)            [N,128]
__device__ float g_h  [(size_t)NN * 128];   // relu(s1 @ W1^T)    [N,128]
__device__ float g_t  [(size_t)NN * 64];    // h @ W2^T           [N,64]
__device__ float g_s2 [(size_t)NN * 64];    // spmm(t)            [N,64]
__device__ float g_W1T[128 * 128];          // W1 transposed, k-major: W1T[k*128+c] = W1[c*128+k]
__device__ float g_W2T[128 * 64];           // W2 transposed, k-major: W2T[k*64+c]  = W2[c*128+k]
__device__ int   g_cnt[NN];
__device__ int   g_rowstart[NN + 1];
__device__ int   g_epos[NN];
__device__ int   g_esrc[EE];
__device__ float g_eval[EE];

// ---------------- CSR build ----------------
__global__ void zero_cnt_k() {
    int i = blockIdx.x * blockDim.x + threadIdx.x;
    if (i < NN) g_cnt[i] = 0;
}

__global__ void hist_k(const int* __restrict__ dst) {
    int e = blockIdx.x * blockDim.x + threadIdx.x;
    if (e < EE) atomicAdd(&g_cnt[dst[e]], 1);
}

// single-block exclusive scan over g_cnt -> g_rowstart / g_epos
__global__ void scan_k() {
    __shared__ int warp_excl[32];
    __shared__ int s_carry;
    const int tid  = threadIdx.x;
    const int lane = tid & 31;
    const int wid  = tid >> 5;
    if (tid == 0) s_carry = 0;
    __syncthreads();

    for (int base = 0; base < NN; base += 1024) {
        int i = base + tid;
        int v = (i < NN) ? g_cnt[i] : 0;
        // warp inclusive scan
        int incl = v;
        #pragma unroll
        for (int off = 1; off < 32; off <<= 1) {
            int t = __shfl_up_sync(0xffffffffu, incl, off);
            if (lane >= off) incl += t;
        }
        if (lane == 31) warp_excl[wid] = incl;   // warp totals
        __syncthreads();
        if (wid == 0) {
            int ws = warp_excl[lane];
            int wincl = ws;
            #pragma unroll
            for (int off = 1; off < 32; off <<= 1) {
                int t = __shfl_up_sync(0xffffffffu, wincl, off);
                if (lane >= off) wincl += t;
            }
            warp_excl[lane] = wincl - ws;        // exclusive prefix of warp sums
        }
        __syncthreads();
        int excl = (incl - v) + warp_excl[wid] + s_carry;
        if (i < NN) { g_rowstart[i] = excl; g_epos[i] = excl; }
        __syncthreads();
        if (tid == 1023) s_carry = excl + v;     // inclusive total so far
        __syncthreads();
    }
    if (threadIdx.x == 0) g_rowstart[NN] = s_carry;  // == EE
}

__global__ void scatter_k(const int* __restrict__ src,
                          const int* __restrict__ dst,
                          const float* __restrict__ vals) {
    int e = blockIdx.x * blockDim.x + threadIdx.x;
    if (e < EE) {
        int d = dst[e];
        int p = atomicAdd(&g_epos[d], 1);
        g_esrc[p] = src[e];
        g_eval[p] = vals[e];
    }
}

// ---------------- one-shot weight transpose (k-major layout for conflict-free GEMM b-loads) ----------------
__global__ void transW_k(const float* __restrict__ W1, const float* __restrict__ W2) {
    int i = blockIdx.x * blockDim.x + threadIdx.x;
    if (i < 128 * 128) {
        int c = i >> 7, k = i & 127;
        g_W1T[k * 128 + c] = W1[i];
    } else {
        int j = i - 128 * 128;
        if (j < 64 * 128) {
            int c = j >> 7, k = j & 127;
            g_W2T[k * 64 + c] = W2[j];
        }
    }
}

// ---------------- gather-only SpMM: one warp per destination node ----------------
template <int F>
__device__ __forceinline__ void spmm_body(const float* __restrict__ xin,
                                          float* __restrict__ out) {
    int gtid = blockIdx.x * blockDim.x + threadIdx.x;
    int w    = gtid >> 5;
    int lane = gtid & 31;
    if (w >= NN) return;
    int beg = g_rowstart[w];
    int end = g_rowstart[w + 1];
    if (F == 128) {
        float4 acc = make_float4(0.f, 0.f, 0.f, 0.f);
        const float4* xb = (const float4*)xin;
        for (int j = beg; j < end; j++) {
            int   s = __ldg(&g_esrc[j]);
            float v = __ldg(&g_eval[j]);
            float4 xv = __ldg(&xb[(size_t)s * 32 + lane]);
            acc.x = fmaf(v, xv.x, acc.x);
            acc.y = fmaf(v, xv.y, acc.y);
            acc.z = fmaf(v, xv.z, acc.z);
            acc.w = fmaf(v, xv.w, acc.w);
        }
        ((float4*)out)[(size_t)w * 32 + lane] = acc;
    } else {
        float2 acc = make_float2(0.f, 0.f);
        const float2* xb = (const float2*)xin;
        for (int j = beg; j < end; j++) {
            int   s = __ldg(&g_esrc[j]);
            float v = __ldg(&g_eval[j]);
            float2 xv = __ldg(&xb[(size_t)s * 32 + lane]);
            acc.x = fmaf(v, xv.x, acc.x);
            acc.y = fmaf(v, xv.y, acc.y);
        }
        ((float2*)out)[(size_t)w * 32 + lane] = acc;
    }
}

__global__ void spmm1_k(const float* __restrict__ x) { spmm_body<128>(x, g_s1); }
__global__ void spmm2_k()                            { spmm_body<64>(g_t, g_s2); }

// ---------------- dense GEMM: out[r][c] = sum_k A[r][k] * BT[k][c], tile 128 rows x NC cols ----------------
// 256 threads, per-thread 8 rows x (NC/16) cols. A-tile padded (stride 132) -> a-loads broadcast;
// b-loads consecutive banks via col = tc + 16*j.
template <int NC, bool RELU>
__device__ __forceinline__ void gemm_body(const float* __restrict__ A,
                                          const float* __restrict__ BT,
                                          float* __restrict__ out) {
    extern __shared__ float sm[];
    float* As = sm;               // [128][132]
    float* Bs = sm + 128 * 132;   // [128][NC] k-major
    const int tid = threadIdx.x;
    const int r0  = blockIdx.x * 128;

    // load A tile (coalesced float4, conflict-free float4 smem stores)
    #pragma unroll
    for (int i = 0; i < 16; i++) {
        int idx = tid + i * 256;           // 0..4095
        int r = idx >> 5, kq = idx & 31;
        float4 v = make_float4(0.f, 0.f, 0.f, 0.f);
        if (r0 + r < NN) v = *(const float4*)(A + (size_t)(r0 + r) * 128 + kq * 4);
        *(float4*)(As + r * 132 + kq * 4) = v;
    }
    // load BT (already k-major in global; straight float4 copy)
    constexpr int NB = (128 * NC) / 4 / 256;
    #pragma unroll
    for (int i = 0; i < NB; i++) {
        int idx = tid + i * 256;
        ((float4*)Bs)[idx] = ((const float4*)BT)[idx];
    }
    __syncthreads();

    constexpr int CPT = NC / 16;
    const int tr = tid >> 4;   // 0..15 row groups
    const int tc = tid & 15;   // 0..15 col groups
    float acc[8][CPT];
    #pragma unroll
    for (int i = 0; i < 8; i++)
        #pragma unroll
        for (int j = 0; j < CPT; j++) acc[i][j] = 0.f;

    const float* Abase = As + tr * 8 * 132;
    const float* Bbase = Bs + tc;

    #pragma unroll 4
    for (int k = 0; k < 128; k++) {
        float a[8], b[CPT];
        #pragma unroll
        for (int i = 0; i < 8; i++) a[i] = Abase[i * 132 + k];
        #pragma unroll
        for (int j = 0; j < CPT; j++) b[j] = Bbase[k * NC + 16 * j];
        #pragma unroll
        for (int i = 0; i < 8; i++)
            #pragma unroll
            for (int j = 0; j < CPT; j++) acc[i][j] = fmaf(a[i], b[j], acc[i][j]);
    }

    #pragma unroll
    for (int i = 0; i < 8; i++) {
        int r = r0 + tr * 8 + i;
        if (r < NN) {
            #pragma unroll
            for (int j = 0; j < CPT; j++) {
                float v = acc[i][j];
                if (RELU) v = fmaxf(v, 0.f);
                out[(size_t)r * NC + tc + 16 * j] = v;
            }
        }
    }
}

__global__ void __launch_bounds__(256) gemm1_k() { gemm_body<128, true >(g_s1, g_W1T, g_h); }
__global__ void __launch_bounds__(256) gemm2_k() { gemm_body<64,  false>(g_h,  g_W2T, g_t); }

// ---------------- softmax: one warp per row of 64 ----------------
__global__ void softmax_k(float* __restrict__ out) {
    int gtid = blockIdx.x * blockDim.x + threadIdx.x;
    int w    = gtid >> 5;
    int lane = gtid & 31;
    if (w >= NN) return;
    float2 v = ((const float2*)g_s2)[(size_t)w * 32 + lane];
    float m = fmaxf(v.x, v.y);
    #pragma unroll
    for (int o = 16; o; o >>= 1) m = fmaxf(m, __shfl_xor_sync(0xffffffffu, m, o));
    float e0 = __expf(v.x - m);
    float e1 = __expf(v.y - m);
    float s = e0 + e1;
    #pragma unroll
    for (int o = 16; o; o >>= 1) s += __shfl_xor_sync(0xffffffffu, s, o);
    float inv = 1.0f / s;
    ((float2*)out)[(size_t)w * 32 + lane] = make_float2(e0 * inv, e1 * inv);
}

// ---------------- launch ----------------
extern "C" void kernel_launch(void* const* d_in, const int* in_sizes, int n_in,
                              void* d_out, int out_size) {
    const float* x    = (const float*)d_in[0];
    const float* vals = (const float*)d_in[1];
    const float* W1   = (const float*)d_in[2];
    const float* W2   = (const float*)d_in[3];
    const int*   src  = (const int*)d_in[4];
    const int*   dst  = (const int*)d_in[5];
    float*       out  = (float*)d_out;

    const int SMEM1 = (128 * 132 + 128 * 128) * 4;  // 133120 B
    const int SMEM2 = (128 * 132 + 128 * 64) * 4;   // 100352 B
    cudaFuncSetAttribute(gemm1_k, cudaFuncAttributeMaxDynamicSharedMemorySize, SMEM1);
    cudaFuncSetAttribute(gemm2_k, cudaFuncAttributeMaxDynamicSharedMemorySize, SMEM2);

    const int TB = 256;
    zero_cnt_k <<<(NN + TB - 1) / TB, TB>>>();
    hist_k     <<<(EE + TB - 1) / TB, TB>>>(dst);
    scan_k     <<<1, 1024>>>();
    scatter_k  <<<(EE + TB - 1) / TB, TB>>>(src, dst, vals);
    transW_k   <<<(128 * 128 + 64 * 128 + TB - 1) / TB, TB>>>(W1, W2);

    spmm1_k    <<<(NN * 32 + TB - 1) / TB, TB>>>(x);
    gemm1_k    <<<(NN + 127) / 128, TB, SMEM1>>>();
    gemm2_k    <<<(NN + 127) / 128, TB, SMEM2>>>();
    spmm2_k    <<<(NN * 32 + TB - 1) / TB, TB>>>();
    softmax_k  <<<(NN * 32 + TB - 1) / TB, TB>>>(out);
}